// round 8
// baseline (speedup 1.0000x reference)
#include <cuda_runtime.h>
#include <math_constants.h>

// Problem constants (fixed shapes for this problem instance)
#define NEWN 65536      // new (coarse) nodes
#define BB   4          // batch
#define VV   64         // feature dim
#define BVN  256        // BB*VV fused columns
#define SPB  32         // segments handled per block
#define SPG  8          // segments per 64-thread group (SPB/4)

// Scratch: segment start offsets (row is sorted, every segment non-empty)
__device__ int g_seg_start[NEWN + 1];

// ---------------------------------------------------------------------------
// Kernel 1: segment boundaries from sorted row[]
// ---------------------------------------------------------------------------
__global__ void build_starts_kernel(const int* __restrict__ row, int nnz) {
    int i = blockIdx.x * blockDim.x + threadIdx.x;
    if (i >= nnz) return;
    int r = row[i];
    if (i == 0) {
        g_seg_start[r] = 0;
    } else if (r != __ldg(row + i - 1)) {
        g_seg_start[r] = i;
    }
    if (i == nnz - 1) g_seg_start[NEWN] = nnz;
}

// Bank-swizzled staging index for argmax node ids.
__device__ __forceinline__ int node_idx(int j, int ml) {
    return j * SPB + ((ml + (j >> 4)) & (SPB - 1));
}

// ---------------------------------------------------------------------------
// Kernel 2: per-segment weighted argmax pool, float4 gathers, 4-way batched.
//
// 256 threads = 4 groups of 64; group g owns segments [8g, 8g+8).
// Within a group: b = tg>>4, v = (tg&15)*4. Per child, the group's 64
// threads cover the full [4 batch x 64 feat] slice of x for that node as
// 4 contiguous 256B runs. Inner scan processes 4 children per iteration
// with predicated independent loads (4x LDG.128 batched before the compare
// chain) -> ~4x bytes in flight vs one-at-a-time. Compares stay in
// ascending-i order, reproducing the reference tie-break exactly.
// ---------------------------------------------------------------------------
__global__ __launch_bounds__(256)
void pool_kernel(const float* __restrict__ x,
                 const float* __restrict__ weights,
                 const int*   __restrict__ col,
                 float* __restrict__ out,
                 int oldN,
                 int write_idx) {
    __shared__ int   s_node[BVN * SPB];   // swizzled [j][ml] argmax nodes (32 KiB)
    __shared__ int   s_abs[SPB + 1];
    __shared__ float s_w[SPB];

    const int t  = threadIdx.x;
    const int g  = t >> 6;                // segment subgroup 0..3
    const int tg = t & 63;
    const int b  = tg >> 4;               // batch 0..3
    const int v  = (tg & 15) << 2;        // feature base 0..60
    const int m0 = blockIdx.x * SPB;

    if (t <= SPB) {
        int st = g_seg_start[m0 + t];
        s_abs[t] = st;
        if (t < SPB) s_w[t] = __ldg(weights + st);
    }
    __syncthreads();

    // this thread's (b, v) float4 slice of x
    const float4* xb = (const float4*)(x + (size_t)b * oldN * VV + v);

    #pragma unroll
    for (int ml = g * SPG; ml < g * SPG + SPG; ++ml) {
        const int   s = s_abs[ml];
        const int   e = s_abs[ml + 1];
        const float w = s_w[ml];

        float4 bwv  = make_float4(-CUDART_INF_F, -CUDART_INF_F,
                                  -CUDART_INF_F, -CUDART_INF_F);
        float4 bval = make_float4(0.f, 0.f, 0.f, 0.f);
        int bn0 = 0, bn1 = 0, bn2 = 0, bn3 = 0;

        for (int i = s; i < e; i += 4) {
            const bool p1 = (i + 1 < e), p2 = (i + 2 < e), p3 = (i + 3 < e);

            // ---- batched independent loads (all issue before compares) ----
            int n0, n1 = 0, n2 = 0, n3 = 0;
            float4 v0, v1, v2, v3;
            n0 = __ldg(col + i);
            if (p1) n1 = __ldg(col + i + 1);
            if (p2) n2 = __ldg(col + i + 2);
            if (p3) n3 = __ldg(col + i + 3);
            v0 = __ldg(xb + n0 * (VV / 4));
            if (p1) v1 = __ldg(xb + n1 * (VV / 4));
            if (p2) v2 = __ldg(xb + n2 * (VV / 4));
            if (p3) v3 = __ldg(xb + n3 * (VV / 4));

            // ---- sequential compares in ascending i (exact tie-break) ----
            float wv;
            wv = w * v0.x; if (wv > bwv.x) { bwv.x = wv; bval.x = v0.x; bn0 = n0; }
            wv = w * v0.y; if (wv > bwv.y) { bwv.y = wv; bval.y = v0.y; bn1 = n0; }
            wv = w * v0.z; if (wv > bwv.z) { bwv.z = wv; bval.z = v0.z; bn2 = n0; }
            wv = w * v0.w; if (wv > bwv.w) { bwv.w = wv; bval.w = v0.w; bn3 = n0; }
            if (p1) {
                wv = w * v1.x; if (wv > bwv.x) { bwv.x = wv; bval.x = v1.x; bn0 = n1; }
                wv = w * v1.y; if (wv > bwv.y) { bwv.y = wv; bval.y = v1.y; bn1 = n1; }
                wv = w * v1.z; if (wv > bwv.z) { bwv.z = wv; bval.z = v1.z; bn2 = n1; }
                wv = w * v1.w; if (wv > bwv.w) { bwv.w = wv; bval.w = v1.w; bn3 = n1; }
            }
            if (p2) {
                wv = w * v2.x; if (wv > bwv.x) { bwv.x = wv; bval.x = v2.x; bn0 = n2; }
                wv = w * v2.y; if (wv > bwv.y) { bwv.y = wv; bval.y = v2.y; bn1 = n2; }
                wv = w * v2.z; if (wv > bwv.z) { bwv.z = wv; bval.z = v2.z; bn2 = n2; }
                wv = w * v2.w; if (wv > bwv.w) { bwv.w = wv; bval.w = v2.w; bn3 = n2; }
            }
            if (p3) {
                wv = w * v3.x; if (wv > bwv.x) { bwv.x = wv; bval.x = v3.x; bn0 = n3; }
                wv = w * v3.y; if (wv > bwv.y) { bwv.y = wv; bval.y = v3.y; bn1 = n3; }
                wv = w * v3.z; if (wv > bwv.z) { bwv.z = wv; bval.z = v3.z; bn2 = n3; }
                wv = w * v3.w; if (wv > bwv.w) { bwv.w = wv; bval.w = v3.w; bn3 = n3; }
            }
        }

        const int m = m0 + ml;
        // x_pooled[b, m, v..v+3] -- STG.128, coalesced
        *(float4*)&out[((size_t)b * NEWN + m) * VV + v] = bval;

        // stage argmax nodes (column j = (v+k)*BB + b), bank-swizzled
        s_node[node_idx((v + 0) * BB + b, ml)] = bn0;
        s_node[node_idx((v + 1) * BB + b, ml)] = bn1;
        s_node[node_idx((v + 2) * BB + b, ml)] = bn2;
        s_node[node_idx((v + 3) * BB + b, ml)] = bn3;
    }

    __syncthreads();
    if (!write_idx) return;                 // uniform across block

    // nnz_ind[0] at out1[j*NEWN + m], nnz_ind[1] = j at out2[same offset].
    float* out1 = out  + (size_t)BB  * NEWN * VV;   // +16,777,216
    float* out2 = out1 + (size_t)BVN * NEWN;        // +16,777,216

    const int jl  = t >> 3;                 // 0..31
    const int mlb = (t & 7) * 4;            // segment chunk base
    #pragma unroll
    for (int it = 0; it < 8; ++it) {
        const int jj = it * 32 + jl;
        float4 f;
        f.x = (float)s_node[node_idx(jj, mlb + 0)];
        f.y = (float)s_node[node_idx(jj, mlb + 1)];
        f.z = (float)s_node[node_idx(jj, mlb + 2)];
        f.w = (float)s_node[node_idx(jj, mlb + 3)];
        const size_t off = (size_t)jj * NEWN + m0 + mlb;
        *(float4*)&out1[off] = f;           // exact: node < 2^24
        const float fj = (float)jj;
        *(float4*)&out2[off] = make_float4(fj, fj, fj, fj);
    }
}

// ---------------------------------------------------------------------------
// Launch
// inputs (metadata order): x f32[B,OLD,V], weights f32[nnz], row i32[nnz],
//                          col i32[nnz], new_nodes i32[1]
// output: concat(x_pooled f32[B,NEWN,V], nnz_ind[2, BV*NEWN])
// ---------------------------------------------------------------------------
extern "C" void kernel_launch(void* const* d_in, const int* in_sizes, int n_in,
                              void* d_out, int out_size) {
    const float* x       = (const float*)d_in[0];
    const float* weights = (const float*)d_in[1];
    const int*   row     = (const int*)d_in[2];
    const int*   col     = (const int*)d_in[3];

    const int nnz  = in_sizes[3];
    const int oldN = in_sizes[0] / (BB * VV);

    build_starts_kernel<<<(nnz + 255) / 256, 256>>>(row, nnz);

    const int pooled_elems = BB * NEWN * VV;                 // 16,777,216
    const int write_idx    = (out_size >= 3 * pooled_elems) ? 1 : 0;

    pool_kernel<<<NEWN / SPB, 256>>>(x, weights, col, (float*)d_out,
                                     oldN, write_idx);
}

// round 9
// speedup vs baseline: 1.0365x; 1.0365x over previous
#include <cuda_runtime.h>
#include <math_constants.h>

// Problem constants (fixed shapes for this problem instance)
#define NEWN 65536      // new (coarse) nodes
#define BB   4          // batch
#define VV   64         // feature dim
#define BVN  256        // BB*VV fused columns
#define SPB  32         // segments handled per block
#define SPG  8          // segments per 64-thread group (SPB/4)
#define CCAP 2048       // staged col capacity (block range avg ~128)

// Scratch: segment start offsets (row is sorted, every segment non-empty)
__device__ int g_seg_start[NEWN + 1];

// ---------------------------------------------------------------------------
// Kernel 1: segment boundaries from sorted row[]
// ---------------------------------------------------------------------------
__global__ void build_starts_kernel(const int* __restrict__ row, int nnz) {
    int i = blockIdx.x * blockDim.x + threadIdx.x;
    if (i >= nnz) return;
    int r = row[i];
    if (i == 0) {
        g_seg_start[r] = 0;
    } else if (r != __ldg(row + i - 1)) {
        g_seg_start[r] = i;
    }
    if (i == nnz - 1) g_seg_start[NEWN] = nnz;
}

// Bank-swizzled staging index for argmax node ids.
__device__ __forceinline__ int node_idx(int j, int ml) {
    return j * SPB + ((ml + (j >> 4)) & (SPB - 1));
}

// ---------------------------------------------------------------------------
// Kernel 2: per-segment weighted argmax pool, float4 gathers, smem-staged col.
//
// 256 threads = 4 groups of 64; group g owns segments [8g, 8g+8).
// Within a group: b = tg>>4, v = (tg&15)*4. The block's whole col range is
// first staged into smem with ONE coalesced pass, so the per-child gather
// address comes from a 29-cycle LDS instead of a ~600-cycle dependent LDG.
// The scan itself is the proven simple per-segment loop (R5, 40 regs):
// with the address chain gone, consecutive LDG.128 gathers pipeline freely.
// Compares run in ascending i with strict > -> bit-exact reference tiebreak.
// ---------------------------------------------------------------------------
__global__ __launch_bounds__(256)
void pool_kernel(const float* __restrict__ x,
                 const float* __restrict__ weights,
                 const int*   __restrict__ col,
                 float* __restrict__ out,
                 int oldN,
                 int write_idx) {
    __shared__ int   s_node[BVN * SPB];   // swizzled [j][ml] argmax nodes (32 KiB)
    __shared__ int   s_col[CCAP];         // staged col entries (8 KiB)
    __shared__ int   s_abs[SPB + 1];
    __shared__ float s_w[SPB];

    const int t  = threadIdx.x;
    const int g  = t >> 6;                // segment subgroup 0..3
    const int tg = t & 63;
    const int b  = tg >> 4;               // batch 0..3
    const int v  = (tg & 15) << 2;        // feature base 0..60
    const int m0 = blockIdx.x * SPB;

    if (t <= SPB) {
        int st = g_seg_start[m0 + t];
        s_abs[t] = st;
        if (t < SPB) s_w[t] = __ldg(weights + st);
    }
    __syncthreads();

    const int s0 = s_abs[0];
    const int L  = s_abs[SPB] - s0;

    // coalesced staging of this block's col range
    for (int i = t; i < L && i < CCAP; i += 256)
        s_col[i] = __ldg(col + s0 + i);
    __syncthreads();

    // this thread's (b, v) float4 slice of x
    const float4* xb = (const float4*)(x + (size_t)b * oldN * VV + v);

    #pragma unroll
    for (int ml = g * SPG; ml < g * SPG + SPG; ++ml) {
        const int   s = s_abs[ml];
        const int   e = s_abs[ml + 1];
        const float w = s_w[ml];

        float4 bwv  = make_float4(-CUDART_INF_F, -CUDART_INF_F,
                                  -CUDART_INF_F, -CUDART_INF_F);
        float4 bval = make_float4(0.f, 0.f, 0.f, 0.f);
        int bn0 = 0, bn1 = 0, bn2 = 0, bn3 = 0;

        for (int i = s; i < e; ++i) {
            const int li   = i - s0;
            const int node = (li < CCAP) ? s_col[li] : __ldg(col + i);
            const float4 val = __ldg(xb + node * (VV / 4));   // LDG.128, coalesced
            // fp32 mul + strict > scan == reference segment_max + min-index tiebreak
            float wv;
            wv = w * val.x; if (wv > bwv.x) { bwv.x = wv; bval.x = val.x; bn0 = node; }
            wv = w * val.y; if (wv > bwv.y) { bwv.y = wv; bval.y = val.y; bn1 = node; }
            wv = w * val.z; if (wv > bwv.z) { bwv.z = wv; bval.z = val.z; bn2 = node; }
            wv = w * val.w; if (wv > bwv.w) { bwv.w = wv; bval.w = val.w; bn3 = node; }
        }

        const int m = m0 + ml;
        // x_pooled[b, m, v..v+3] -- STG.128, coalesced
        *(float4*)&out[((size_t)b * NEWN + m) * VV + v] = bval;

        // stage argmax nodes (column j = (v+k)*BB + b), bank-swizzled
        s_node[node_idx((v + 0) * BB + b, ml)] = bn0;
        s_node[node_idx((v + 1) * BB + b, ml)] = bn1;
        s_node[node_idx((v + 2) * BB + b, ml)] = bn2;
        s_node[node_idx((v + 3) * BB + b, ml)] = bn3;
    }

    __syncthreads();
    if (!write_idx) return;                 // uniform across block

    // nnz_ind[0] at out1[j*NEWN + m], nnz_ind[1] = j at out2[same offset].
    float* out1 = out  + (size_t)BB  * NEWN * VV;   // +16,777,216
    float* out2 = out1 + (size_t)BVN * NEWN;        // +16,777,216

    const int jl  = t >> 3;                 // 0..31
    const int mlb = (t & 7) * 4;            // segment chunk base
    #pragma unroll
    for (int it = 0; it < 8; ++it) {
        const int jj = it * 32 + jl;
        float4 f;
        f.x = (float)s_node[node_idx(jj, mlb + 0)];
        f.y = (float)s_node[node_idx(jj, mlb + 1)];
        f.z = (float)s_node[node_idx(jj, mlb + 2)];
        f.w = (float)s_node[node_idx(jj, mlb + 3)];
        const size_t off = (size_t)jj * NEWN + m0 + mlb;
        *(float4*)&out1[off] = f;           // exact: node < 2^24
        const float fj = (float)jj;
        *(float4*)&out2[off] = make_float4(fj, fj, fj, fj);
    }
}

// ---------------------------------------------------------------------------
// Launch
// inputs (metadata order): x f32[B,OLD,V], weights f32[nnz], row i32[nnz],
//                          col i32[nnz], new_nodes i32[1]
// output: concat(x_pooled f32[B,NEWN,V], nnz_ind[2, BV*NEWN])
// ---------------------------------------------------------------------------
extern "C" void kernel_launch(void* const* d_in, const int* in_sizes, int n_in,
                              void* d_out, int out_size) {
    const float* x       = (const float*)d_in[0];
    const float* weights = (const float*)d_in[1];
    const int*   row     = (const int*)d_in[2];
    const int*   col     = (const int*)d_in[3];

    const int nnz  = in_sizes[3];
    const int oldN = in_sizes[0] / (BB * VV);

    build_starts_kernel<<<(nnz + 255) / 256, 256>>>(row, nnz);

    const int pooled_elems = BB * NEWN * VV;                 // 16,777,216
    const int write_idx    = (out_size >= 3 * pooled_elems) ? 1 : 0;

    pool_kernel<<<NEWN / SPB, 256>>>(x, weights, col, (float*)d_out,
                                     oldN, write_idx);
}

// round 13
// speedup vs baseline: 1.1429x; 1.1027x over previous
#include <cuda_runtime.h>
#include <math_constants.h>

// Problem constants (fixed shapes for this problem instance)
#define NEWN 65536      // new (coarse) nodes
#define BB   4          // batch
#define VV   64         // feature dim
#define BVN  256        // BB*VV fused columns
#define SPB  32         // segments handled per block
#define SPG  8          // segments per 64-thread group (SPB/4)
#define CCAP 2048       // staged col capacity (block range avg ~128)

// Scratch: segment start offsets (row is sorted, every segment non-empty)
__device__ int g_seg_start[NEWN + 1];

// ---------------------------------------------------------------------------
// Kernel 1: segment boundaries from sorted row[]
// ---------------------------------------------------------------------------
__global__ void build_starts_kernel(const int* __restrict__ row, int nnz) {
    int i = blockIdx.x * blockDim.x + threadIdx.x;
    if (i >= nnz) return;
    int r = row[i];
    if (i == 0) {
        g_seg_start[r] = 0;
    } else if (r != __ldg(row + i - 1)) {
        g_seg_start[r] = i;
    }
    if (i == nnz - 1) g_seg_start[NEWN] = nnz;
}

// Bank-swizzled staging index for argmax node ids.
__device__ __forceinline__ int node_idx(int j, int ml) {
    return j * SPB + ((ml + (j >> 4)) & (SPB - 1));
}

// ---------------------------------------------------------------------------
// Kernel 2: argmax pool. col staged in smem (LDS addresses) + 4-wide batched
// independent LDG.128 gathers = ~4 gathers in flight per thread.
//
// 256 threads = 4 groups of 64; group g owns segments [8g, 8g+8).
// Within a group: b = tg>>4, v = (tg&15)*4. The block's col range is staged
// into smem with one coalesced pass; the inner scan then issues 4 predicated
// independent x-gathers per iteration whose addresses come from 29-cycle LDS
// (nothing memory-long in front of them). Compares run sequentially in
// ascending i with strict > on w*val -> bit-exact reference tiebreak.
// ---------------------------------------------------------------------------
__global__ __launch_bounds__(256)
void pool_kernel(const float* __restrict__ x,
                 const float* __restrict__ weights,
                 const int*   __restrict__ col,
                 float* __restrict__ out,
                 int oldN,
                 int write_idx) {
    __shared__ int   s_node[BVN * SPB];   // swizzled [j][ml] argmax nodes (32 KiB)
    __shared__ int   s_col[CCAP];         // staged col entries (8 KiB)
    __shared__ int   s_abs[SPB + 1];
    __shared__ float s_w[SPB];

    const int t  = threadIdx.x;
    const int g  = t >> 6;                // segment subgroup 0..3
    const int tg = t & 63;
    const int b  = tg >> 4;               // batch 0..3
    const int v  = (tg & 15) << 2;        // feature base 0..60
    const int m0 = blockIdx.x * SPB;

    if (t <= SPB) {
        int st = g_seg_start[m0 + t];
        s_abs[t] = st;
        if (t < SPB) s_w[t] = __ldg(weights + st);
    }
    __syncthreads();

    const int s0 = s_abs[0];
    const int L  = s_abs[SPB] - s0;

    // coalesced staging of this block's col range
    for (int i = t; i < L && i < CCAP; i += 256)
        s_col[i] = __ldg(col + s0 + i);
    __syncthreads();

    // this thread's (b, v) float4 slice of x
    const float4* xb = (const float4*)(x + (size_t)b * oldN * VV + v);

    #pragma unroll
    for (int ml = g * SPG; ml < g * SPG + SPG; ++ml) {
        const int   s = s_abs[ml];
        const int   e = s_abs[ml + 1];
        const float w = s_w[ml];

        float4 bwv  = make_float4(-CUDART_INF_F, -CUDART_INF_F,
                                  -CUDART_INF_F, -CUDART_INF_F);
        float4 bval = make_float4(0.f, 0.f, 0.f, 0.f);
        int bn0 = 0, bn1 = 0, bn2 = 0, bn3 = 0;

        for (int i = s; i < e; i += 4) {
            const bool p1 = (i + 1 < e), p2 = (i + 2 < e), p3 = (i + 3 < e);

            // ---- addresses from smem (cheap), 4 independent LDG.128 ----
            int n0, n1 = 0, n2 = 0, n3 = 0;
            {
                const int li = i - s0;
                n0 = (li < CCAP) ? s_col[li] : __ldg(col + i);
                if (p1) n1 = (li + 1 < CCAP) ? s_col[li + 1] : __ldg(col + i + 1);
                if (p2) n2 = (li + 2 < CCAP) ? s_col[li + 2] : __ldg(col + i + 2);
                if (p3) n3 = (li + 3 < CCAP) ? s_col[li + 3] : __ldg(col + i + 3);
            }
            float4 v0, v1, v2, v3;
            v0 = __ldg(xb + n0 * (VV / 4));
            if (p1) v1 = __ldg(xb + n1 * (VV / 4));
            if (p2) v2 = __ldg(xb + n2 * (VV / 4));
            if (p3) v3 = __ldg(xb + n3 * (VV / 4));

            // ---- sequential compares in ascending i (exact tie-break) ----
            float wv;
            wv = w * v0.x; if (wv > bwv.x) { bwv.x = wv; bval.x = v0.x; bn0 = n0; }
            wv = w * v0.y; if (wv > bwv.y) { bwv.y = wv; bval.y = v0.y; bn1 = n0; }
            wv = w * v0.z; if (wv > bwv.z) { bwv.z = wv; bval.z = v0.z; bn2 = n0; }
            wv = w * v0.w; if (wv > bwv.w) { bwv.w = wv; bval.w = v0.w; bn3 = n0; }
            if (p1) {
                wv = w * v1.x; if (wv > bwv.x) { bwv.x = wv; bval.x = v1.x; bn0 = n1; }
                wv = w * v1.y; if (wv > bwv.y) { bwv.y = wv; bval.y = v1.y; bn1 = n1; }
                wv = w * v1.z; if (wv > bwv.z) { bwv.z = wv; bval.z = v1.z; bn2 = n1; }
                wv = w * v1.w; if (wv > bwv.w) { bwv.w = wv; bval.w = v1.w; bn3 = n1; }
            }
            if (p2) {
                wv = w * v2.x; if (wv > bwv.x) { bwv.x = wv; bval.x = v2.x; bn0 = n2; }
                wv = w * v2.y; if (wv > bwv.y) { bwv.y = wv; bval.y = v2.y; bn1 = n2; }
                wv = w * v2.z; if (wv > bwv.z) { bwv.z = wv; bval.z = v2.z; bn2 = n2; }
                wv = w * v2.w; if (wv > bwv.w) { bwv.w = wv; bval.w = v2.w; bn3 = n2; }
            }
            if (p3) {
                wv = w * v3.x; if (wv > bwv.x) { bwv.x = wv; bval.x = v3.x; bn0 = n3; }
                wv = w * v3.y; if (wv > bwv.y) { bwv.y = wv; bval.y = v3.y; bn1 = n3; }
                wv = w * v3.z; if (wv > bwv.z) { bwv.z = wv; bval.z = v3.z; bn2 = n3; }
                wv = w * v3.w; if (wv > bwv.w) { bwv.w = wv; bval.w = v3.w; bn3 = n3; }
            }
        }

        const int m = m0 + ml;
        // x_pooled[b, m, v..v+3] -- STG.128, coalesced
        *(float4*)&out[((size_t)b * NEWN + m) * VV + v] = bval;

        // stage argmax nodes (column j = (v+k)*BB + b), bank-swizzled
        s_node[node_idx((v + 0) * BB + b, ml)] = bn0;
        s_node[node_idx((v + 1) * BB + b, ml)] = bn1;
        s_node[node_idx((v + 2) * BB + b, ml)] = bn2;
        s_node[node_idx((v + 3) * BB + b, ml)] = bn3;
    }

    __syncthreads();
    if (!write_idx) return;                 // uniform across block

    // nnz_ind[0] at out1[j*NEWN + m], nnz_ind[1] = j at out2[same offset].
    float* out1 = out  + (size_t)BB  * NEWN * VV;   // +16,777,216
    float* out2 = out1 + (size_t)BVN * NEWN;        // +16,777,216

    const int jl  = t >> 3;                 // 0..31
    const int mlb = (t & 7) * 4;            // segment chunk base
    #pragma unroll
    for (int it = 0; it < 8; ++it) {
        const int jj = it * 32 + jl;
        float4 f;
        f.x = (float)s_node[node_idx(jj, mlb + 0)];
        f.y = (float)s_node[node_idx(jj, mlb + 1)];
        f.z = (float)s_node[node_idx(jj, mlb + 2)];
        f.w = (float)s_node[node_idx(jj, mlb + 3)];
        const size_t off = (size_t)jj * NEWN + m0 + mlb;
        *(float4*)&out1[off] = f;           // exact: node < 2^24
        const float fj = (float)jj;
        *(float4*)&out2[off] = make_float4(fj, fj, fj, fj);
    }
}

// ---------------------------------------------------------------------------
// Launch
// inputs (metadata order): x f32[B,OLD,V], weights f32[nnz], row i32[nnz],
//                          col i32[nnz], new_nodes i32[1]
// output: concat(x_pooled f32[B,NEWN,V], nnz_ind[2, BV*NEWN])
// ---------------------------------------------------------------------------
extern "C" void kernel_launch(void* const* d_in, const int* in_sizes, int n_in,
                              void* d_out, int out_size) {
    const float* x       = (const float*)d_in[0];
    const float* weights = (const float*)d_in[1];
    const int*   row     = (const int*)d_in[2];
    const int*   col     = (const int*)d_in[3];

    const int nnz  = in_sizes[3];
    const int oldN = in_sizes[0] / (BB * VV);

    build_starts_kernel<<<(nnz + 255) / 256, 256>>>(row, nnz);

    const int pooled_elems = BB * NEWN * VV;                 // 16,777,216
    const int write_idx    = (out_size >= 3 * pooled_elems) ? 1 : 0;

    pool_kernel<<<NEWN / SPB, 256>>>(x, weights, col, (float*)d_out,
                                     oldN, write_idx);
}